// round 11
// baseline (speedup 1.0000x reference)
#include <cuda_runtime.h>
#include <cuda_fp16.h>
#include <cstdint>

// Problem shape (fixed for this registry entry)
#define B_  8
#define N_  2048
#define C_  64
#define H_  4
#define D_  64
#define HD_ 256          // H*D
#define NW_ (N_/32)      // mask words per row = 64
#define LOG2E 1.4426950408889634f

// ---------------- scratch (device globals: no allocation allowed) -----------
__device__ __half  g_hH [B_*H_*N_*D_];    // layer1 features, f16 hi
__device__ __half  g_hL [B_*H_*N_*D_];    // layer1 features, f16 lo (residual)
__device__ __half  g_h2H[B_*N_*D_];       // layer2 features hi
__device__ __half  g_h2L[B_*N_*D_];       // layer2 features lo
__device__ float    g_z  [B_*N_*HD_];     // concat+lrelu of layer-1 output
__device__ unsigned g_maskT[NW_*N_];      // transposed bitmask [w][n]

__device__ __forceinline__ float ex2(float x) {
    float y;
    asm("ex2.approx.f32 %0, %1;" : "=f"(y) : "f"(x));
    return y;
}
__device__ __forceinline__ uint32_t smem_u32(const void* p) {
    uint32_t a;
    asm("{ .reg .u64 t; cvta.to.shared.u64 t, %1; cvt.u32.u64 %0, t; }" : "=r"(a) : "l"(p));
    return a;
}
__device__ __forceinline__ void cp16(uint32_t saddr, const void* g) {
    asm volatile("cp.async.ca.shared.global [%0], [%1], 16;"
                 :: "r"(saddr), "l"(__cvta_generic_to_global(g)));
}
__device__ __forceinline__ void ldsm4(uint32_t r[4], uint32_t addr) {
    asm volatile("ldmatrix.sync.aligned.m8n8.x4.shared.b16 {%0,%1,%2,%3}, [%4];"
                 : "=r"(r[0]), "=r"(r[1]), "=r"(r[2]), "=r"(r[3]) : "r"(addr));
}
__device__ __forceinline__ void ldsm4t(uint32_t r[4], uint32_t addr) {
    asm volatile("ldmatrix.sync.aligned.m8n8.x4.trans.shared.b16 {%0,%1,%2,%3}, [%4];"
                 : "=r"(r[0]), "=r"(r[1]), "=r"(r[2]), "=r"(r[3]) : "r"(addr));
}
__device__ __forceinline__ void mma16816(float d[4], const uint32_t a[4], const uint32_t b[2]) {
    asm volatile("mma.sync.aligned.m16n8k16.row.col.f32.f16.f16.f32 "
                 "{%0,%1,%2,%3}, {%4,%5,%6,%7}, {%8,%9}, {%0,%1,%2,%3};"
                 : "+f"(d[0]), "+f"(d[1]), "+f"(d[2]), "+f"(d[3])
                 : "r"(a[0]), "r"(a[1]), "r"(a[2]), "r"(a[3]), "r"(b[0]), "r"(b[1]));
}
__device__ __forceinline__ float lrelu(float a) { return a > 0.f ? a : 0.2f * a; }

__device__ __forceinline__ void split_store(__half* dH, __half* dL, size_t idx,
                                            float v0, float v1) {
    __half h0 = __float2half_rn(v0), h1 = __float2half_rn(v1);
    __half l0 = __float2half_rn(v0 - __half2float(h0));
    __half l1 = __float2half_rn(v1 - __half2float(h1));
    *(__half2*)&dH[idx] = __halves2half2(h0, h1);
    *(__half2*)&dL[idx] = __halves2half2(l0, l1);
}

// ---------------- mask build ------------------------------------------------
__global__ void build_mask_kernel(const int* __restrict__ graph) {
    int gwarp = (blockIdx.x * blockDim.x + threadIdx.x) >> 5;
    int lane  = threadIdx.x & 31;
    if (gwarp >= N_ * NW_) return;
    int n = gwarp >> 6;
    int w = gwarp & (NW_ - 1);
    int m = w * 32 + lane;
    bool bit = (graph[(size_t)n * N_ + m] != 0) || (m == n);
    unsigned word = __ballot_sync(0xffffffffu, bit);
    if (lane == 0) g_maskT[w * N_ + n] = word;
}

// ---------------- proj1: one head per blockIdx.y (grid 256 x 4) -------------
__global__ void proj1_kernel(const float* __restrict__ x,
                             const float* __restrict__ Wh) {
    __shared__ float xs[64][65];
    __shared__ float ws[64][65];
    int t    = threadIdx.x;              // 256 threads
    int row0 = blockIdx.x * 64;          // flattened b*N + n
    int h    = blockIdx.y;
    for (int i = t; i < 64 * 64; i += 256) {
        int r = i >> 6, c = i & 63;
        xs[r][c] = x[(size_t)(row0 + r) * C_ + c];
        ws[r][c] = Wh[((size_t)h * D_ + r) * C_ + c];
    }
    __syncthreads();
    int d0 = (t & 15) * 4;
    int r0 = (t >> 4) * 4;
    int b     = row0 >> 11;
    int nbase = row0 & (N_ - 1);
    float acc[4][4] = {};
    #pragma unroll 8
    for (int c = 0; c < 64; ++c) {
        float xv[4], wv[4];
        #pragma unroll
        for (int i = 0; i < 4; ++i) { xv[i] = xs[r0 + i][c]; wv[i] = ws[d0 + i][c]; }
        #pragma unroll
        for (int i = 0; i < 4; ++i)
            #pragma unroll
            for (int j = 0; j < 4; ++j)
                acc[i][j] += xv[i] * wv[j];
    }
    #pragma unroll
    for (int i = 0; i < 4; ++i) {
        size_t base = (((size_t)(b * H_ + h) * N_) + nbase + r0 + i) * D_ + d0;
        split_store(g_hH, g_hL, base,     acc[i][0], acc[i][1]);
        split_store(g_hH, g_hL, base + 2, acc[i][2], acc[i][3]);
    }
}

// ---------------- proj2: 256 threads, 4x4 micro-tile ------------------------
__global__ void proj2_kernel(const float* __restrict__ Wo) {
    __shared__ float zs[64][65];
    __shared__ float ws[64][65];
    int t    = threadIdx.x;
    int row0 = blockIdx.x * 64;
    int d0 = (t & 15) * 4;
    int r0 = (t >> 4) * 4;
    float acc[4][4] = {};
    for (int kc = 0; kc < 4; ++kc) {
        __syncthreads();
        for (int i = t; i < 64 * 64; i += 256) {
            int r = i >> 6, c = i & 63;
            zs[r][c] = g_z[(size_t)(row0 + r) * HD_ + kc * 64 + c];
            ws[r][c] = Wo[(size_t)r * HD_ + kc * 64 + c];
        }
        __syncthreads();
        #pragma unroll 8
        for (int c = 0; c < 64; ++c) {
            float xv[4], wv[4];
            #pragma unroll
            for (int i = 0; i < 4; ++i) { xv[i] = zs[r0 + i][c]; wv[i] = ws[d0 + i][c]; }
            #pragma unroll
            for (int i = 0; i < 4; ++i)
                #pragma unroll
                for (int j = 0; j < 4; ++j)
                    acc[i][j] += xv[i] * wv[j];
        }
    }
    #pragma unroll
    for (int i = 0; i < 4; ++i) {
        size_t base = (size_t)(row0 + r0 + i) * D_ + d0;
        split_store(g_h2H, g_h2L, base,     acc[i][0], acc[i][1]);
        split_store(g_h2H, g_h2L, base + 2, acc[i][2], acc[i][3]);
    }
}

// ================= HMMA flash attention, 4 warps / 64 rows ===================
// KV tile = 64 cols, 3-deep cp.async ring (KH only), 3 blocks/SM.
// S = Qh*Kh + Ql*Kh = (Qh+Ql)*Kh  (Q split in register frags; K hi-only),
// P f16, O = P*Vh. Same error magnitude as R10 but half the K staging traffic
// and half the GEMM-S ldsm (each K frag reused for qh and ql).
#define SQ 72                          // smem row stride in halves
#define NT 32                          // KV tiles
#define SM_QH 0
#define SM_QL 4608
#define SM_K  9216                     // ring starts after QH/QL
#define KBUF_HALVES 4608               // KH[64][72]
#define SMEM_ATT ((9216 + 3 * KBUF_HALVES) * 2)   // 46080 bytes

template <int LAYER>
__global__ void __launch_bounds__(128, 3)
attn_mma(const float* __restrict__ bias,
         const float* __restrict__ gamma,
         const float* __restrict__ beta,
         float* __restrict__ outp) {
    extern __shared__ __half smh[];
    const int t    = threadIdx.x;
    const int wid  = t >> 5;            // 0..3
    const int lane = t & 31;
    const int g    = lane >> 2;
    const int tg   = lane & 3;
    const int wr0  = wid << 4;
    const int bh   = blockIdx.x;
    const int row0 = blockIdx.y << 6;   // 64 query rows per block
    const __half* hH = (LAYER == 1 ? g_hH : g_h2H) + (size_t)bh * (N_ * D_);
    const __half* hL = (LAYER == 1 ? g_hL : g_h2L) + (size_t)bh * (N_ * D_);
    const uint32_t sbase = smem_u32(smh);

    // ---- stage Q hi + lo (64 rows) via plain loads ----
    {
        const uint4* sH = (const uint4*)(hH + (size_t)row0 * D_);
        const uint4* sL = (const uint4*)(hL + (size_t)row0 * D_);
        #pragma unroll
        for (int i = 0; i < 4; ++i) {
            int idx = t + (i << 7);            // 0..511
            int r = idx >> 3, c8 = (idx & 7) << 3;
            *(uint4*)&smh[SM_QH + r * SQ + c8] = sH[idx];
            *(uint4*)&smh[SM_QL + r * SQ + c8] = sL[idx];
        }
    }
    // ---- prefetch K tiles 0,1 (hi only) into ring buffers 0,1 ----
    #pragma unroll
    for (int pt = 0; pt < 2; ++pt) {
        const uint4* sH = (const uint4*)(hH + (size_t)pt * (64 * D_));
        uint32_t kb = sbase + (uint32_t)(SM_K + pt * KBUF_HALVES) * 2;
        #pragma unroll
        for (int i = 0; i < 4; ++i) {
            int idx = t + (i << 7);            // 0..511
            int r = idx >> 3, c8 = (idx & 7) << 3;
            cp16(kb + (((uint32_t)(r * SQ + c8)) << 1), sH + idx);
        }
        asm volatile("cp.async.commit_group;" ::: "memory");
    }
    __syncthreads();

    // ---- preload Q A-frags (hi and lo) ----
    uint32_t qh[4][4], ql[4][4];
    {
        int arow  = wr0 + (lane & 15);
        int acolb = (lane >> 4) << 3;
        #pragma unroll
        for (int kf = 0; kf < 4; ++kf) {
            ldsm4(qh[kf], sbase + ((uint32_t)(SM_QH + arow * SQ + (kf << 4) + acolb) << 1));
            ldsm4(ql[kf], sbase + ((uint32_t)(SM_QL + arow * SQ + (kf << 4) + acolb) << 1));
        }
    }

    float oacc[8][4];
    #pragma unroll
    for (int i = 0; i < 8; ++i)
        #pragma unroll
        for (int j = 0; j < 4; ++j) oacc[i][j] = 0.f;
    float rs0 = 0.f, rs1 = 0.f, mr0 = -1e30f, mr1 = -1e30f;
    const int grow0 = row0 + wr0 + g;

    int buf = 0;
    #pragma unroll 1
    for (int tile = 0; tile < NT; ++tile) {
        asm volatile("cp.async.wait_group 1;" ::: "memory");
        __syncthreads();
        // ---- prefetch tile+2 into ring slot ----
        {
            int pt = tile + 2;
            if (pt < NT) {
                int pb = buf + 2; if (pb >= 3) pb -= 3;
                const uint4* sH = (const uint4*)(hH + (size_t)pt * (64 * D_));
                uint32_t kb = sbase + (uint32_t)(SM_K + pb * KBUF_HALVES) * 2;
                #pragma unroll
                for (int i = 0; i < 4; ++i) {
                    int idx = t + (i << 7);
                    int r = idx >> 3, c8 = (idx & 7) << 3;
                    cp16(kb + (((uint32_t)(r * SQ + c8)) << 1), sH + idx);
                }
            }
            asm volatile("cp.async.commit_group;" ::: "memory");   // empty group ok
        }
        unsigned mw0[2], mw1[2];
        #pragma unroll
        for (int w = 0; w < 2; ++w) {
            mw0[w] = g_maskT[(size_t)((tile << 1) + w) * N_ + grow0];
            mw1[w] = g_maskT[(size_t)((tile << 1) + w) * N_ + grow0 + 8];
        }

        const uint32_t kbH = sbase + (uint32_t)(SM_K + buf * KBUF_HALVES) * 2;

        // ---- GEMM-S: sacc = (Qh + Ql) * Kh ; K frags reused for both terms ----
        float sacc[8][4];
        #pragma unroll
        for (int i = 0; i < 8; ++i)
            #pragma unroll
            for (int j = 0; j < 4; ++j) sacc[i][j] = 0.f;
        {
            const int brow = ((lane >> 4) << 3) + (lane & 7);
            const int bcol = ((lane >> 3) & 1) << 3;
            #pragma unroll
            for (int kf = 0; kf < 4; ++kf) {
                uint32_t bfr[8][2];
                #pragma unroll
                for (int j = 0; j < 4; ++j) {
                    uint32_t r4[4];
                    ldsm4(r4, kbH + ((uint32_t)(((j << 4) + brow) * SQ
                                                + (kf << 4) + bcol) << 1));
                    bfr[2*j][0] = r4[0]; bfr[2*j][1] = r4[1];
                    bfr[2*j+1][0] = r4[2]; bfr[2*j+1][1] = r4[3];
                }
                #pragma unroll
                for (int nf = 0; nf < 8; ++nf) mma16816(sacc[nf], qh[kf], bfr[nf]);
                #pragma unroll
                for (int nf = 0; nf < 8; ++nf) mma16816(sacc[nf], ql[kf], bfr[nf]);
            }
        }

        // ---- masked online softmax; P -> A-frags in registers ----
        float m0 = -1e30f, m1 = -1e30f;
        #pragma unroll
        for (int nf = 0; nf < 8; ++nf) {
            unsigned w0 = mw0[nf >> 2], w1 = mw1[nf >> 2];
            int bb = ((nf & 3) << 3) + (tg << 1);
            m0 = fmaxf(m0, ((w0 >> bb) & 1u)       ? sacc[nf][0] : -1e30f);
            m0 = fmaxf(m0, ((w0 >> (bb + 1)) & 1u) ? sacc[nf][1] : -1e30f);
            m1 = fmaxf(m1, ((w1 >> bb) & 1u)       ? sacc[nf][2] : -1e30f);
            m1 = fmaxf(m1, ((w1 >> (bb + 1)) & 1u) ? sacc[nf][3] : -1e30f);
        }
        m0 = fmaxf(m0, __shfl_xor_sync(0xffffffffu, m0, 1));
        m0 = fmaxf(m0, __shfl_xor_sync(0xffffffffu, m0, 2));
        m1 = fmaxf(m1, __shfl_xor_sync(0xffffffffu, m1, 1));
        m1 = fmaxf(m1, __shfl_xor_sync(0xffffffffu, m1, 2));
        float mn0 = fmaxf(mr0, m0), mn1 = fmaxf(mr1, m1);
        float al0 = ex2((mr0 - mn0) * LOG2E), al1 = ex2((mr1 - mn1) * LOG2E);
        mr0 = mn0; mr1 = mn1;
        rs0 *= al0; rs1 *= al1;
        #pragma unroll
        for (int nf = 0; nf < 8; ++nf) {
            oacc[nf][0] *= al0; oacc[nf][1] *= al0;
            oacc[nf][2] *= al1; oacc[nf][3] *= al1;
        }
        const float mL0 = mn0 * LOG2E, mL1 = mn1 * LOG2E;
        uint32_t pa[4][4];
        #pragma unroll
        for (int k2 = 0; k2 < 4; ++k2) {
            int nfA = k2 << 1, nfB = nfA + 1;
            unsigned wA0 = mw0[nfA >> 2], wA1 = mw1[nfA >> 2];
            unsigned wB0 = mw0[nfB >> 2], wB1 = mw1[nfB >> 2];
            int bbA = ((nfA & 3) << 3) + (tg << 1);
            int bbB = ((nfB & 3) << 3) + (tg << 1);
            float p00 = ((wA0 >> bbA) & 1u)     ? ex2(fmaf(sacc[nfA][0], LOG2E, -mL0)) : 0.f;
            float p01 = ((wA0 >> (bbA+1)) & 1u) ? ex2(fmaf(sacc[nfA][1], LOG2E, -mL0)) : 0.f;
            float p02 = ((wA1 >> bbA) & 1u)     ? ex2(fmaf(sacc[nfA][2], LOG2E, -mL1)) : 0.f;
            float p03 = ((wA1 >> (bbA+1)) & 1u) ? ex2(fmaf(sacc[nfA][3], LOG2E, -mL1)) : 0.f;
            float p10 = ((wB0 >> bbB) & 1u)     ? ex2(fmaf(sacc[nfB][0], LOG2E, -mL0)) : 0.f;
            float p11 = ((wB0 >> (bbB+1)) & 1u) ? ex2(fmaf(sacc[nfB][1], LOG2E, -mL0)) : 0.f;
            float p12 = ((wB1 >> bbB) & 1u)     ? ex2(fmaf(sacc[nfB][2], LOG2E, -mL1)) : 0.f;
            float p13 = ((wB1 >> (bbB+1)) & 1u) ? ex2(fmaf(sacc[nfB][3], LOG2E, -mL1)) : 0.f;
            __half2 h0 = __floats2half2_rn(p00, p01);
            __half2 h1 = __floats2half2_rn(p02, p03);
            __half2 h2 = __floats2half2_rn(p10, p11);
            __half2 h3 = __floats2half2_rn(p12, p13);
            pa[k2][0] = *(uint32_t*)&h0; pa[k2][1] = *(uint32_t*)&h1;
            pa[k2][2] = *(uint32_t*)&h2; pa[k2][3] = *(uint32_t*)&h3;
            float2 f0 = __half22float2(h0), f2 = __half22float2(h2);
            float2 f1 = __half22float2(h1), f3 = __half22float2(h3);
            rs0 += (f0.x + f0.y) + (f2.x + f2.y);
            rs1 += (f1.x + f1.y) + (f3.x + f3.y);
        }

        // ---- GEMM-A: O += P * Vh ----
        {
            const int brow  = (((lane >> 3) & 1) << 3) + (lane & 7);
            const int bcolb = (lane >> 4) << 3;
            #pragma unroll
            for (int kf = 0; kf < 4; ++kf) {
                uint32_t bv[8][2];
                #pragma unroll
                for (int j = 0; j < 4; ++j) {
                    uint32_t r4[4];
                    ldsm4t(r4, kbH + ((uint32_t)(((kf << 4) + brow) * SQ
                                                 + (j << 4) + bcolb) << 1));
                    bv[2*j][0] = r4[0]; bv[2*j][1] = r4[1];
                    bv[2*j+1][0] = r4[2]; bv[2*j+1][1] = r4[3];
                }
                #pragma unroll
                for (int nf = 0; nf < 8; ++nf) mma16816(oacc[nf], pa[kf], bv[nf]);
            }
        }
        if (++buf == 3) buf = 0;
    }

    // ---- finalize ----
    rs0 += __shfl_xor_sync(0xffffffffu, rs0, 1);
    rs0 += __shfl_xor_sync(0xffffffffu, rs0, 2);
    rs1 += __shfl_xor_sync(0xffffffffu, rs1, 1);
    rs1 += __shfl_xor_sync(0xffffffffu, rs1, 2);
    float inv0 = 1.f / rs0, inv1 = 1.f / rs1;

    if (LAYER == 1) {
        int h = bh & (H_ - 1);
        int b = bh >> 2;
        size_t rbase = ((size_t)b * N_ + grow0) * HD_ + h * D_;
        #pragma unroll
        for (int nf = 0; nf < 8; ++nf) {
            int c = (nf << 3) + (tg << 1);
            float b0v = bias[h * D_ + c], b1v = bias[h * D_ + c + 1];
            float2 v0, v1;
            v0.x = lrelu(fmaf(oacc[nf][0], inv0, b0v));
            v0.y = lrelu(fmaf(oacc[nf][1], inv0, b1v));
            v1.x = lrelu(fmaf(oacc[nf][2], inv1, b0v));
            v1.y = lrelu(fmaf(oacc[nf][3], inv1, b1v));
            *(float2*)&g_z[rbase + c]           = v0;
            *(float2*)&g_z[rbase + 8 * HD_ + c] = v1;
        }
    } else {
        float v0[16], v1[16];
        float s0 = 0.f, s1 = 0.f;
        #pragma unroll
        for (int nf = 0; nf < 8; ++nf) {
            int c = (nf << 3) + (tg << 1);
            float b0v = bias[c], b1v = bias[c + 1];
            float a;
            a = lrelu(fmaf(oacc[nf][0], inv0, b0v)); v0[2*nf]   = a; s0 += a;
            a = lrelu(fmaf(oacc[nf][1], inv0, b1v)); v0[2*nf+1] = a; s0 += a;
            a = lrelu(fmaf(oacc[nf][2], inv1, b0v)); v1[2*nf]   = a; s1 += a;
            a = lrelu(fmaf(oacc[nf][3], inv1, b1v)); v1[2*nf+1] = a; s1 += a;
        }
        s0 += __shfl_xor_sync(0xffffffffu, s0, 1);
        s0 += __shfl_xor_sync(0xffffffffu, s0, 2);
        s1 += __shfl_xor_sync(0xffffffffu, s1, 1);
        s1 += __shfl_xor_sync(0xffffffffu, s1, 2);
        float mu0 = s0 * (1.f / 64.f), mu1 = s1 * (1.f / 64.f);
        float q0 = 0.f, q1 = 0.f;
        #pragma unroll
        for (int i = 0; i < 16; ++i) {
            float u0 = v0[i] - mu0; q0 += u0 * u0;
            float u1 = v1[i] - mu1; q1 += u1 * u1;
        }
        q0 += __shfl_xor_sync(0xffffffffu, q0, 1);
        q0 += __shfl_xor_sync(0xffffffffu, q0, 2);
        q1 += __shfl_xor_sync(0xffffffffu, q1, 1);
        q1 += __shfl_xor_sync(0xffffffffu, q1, 2);
        float rstd0 = rsqrtf(q0 * (1.f / 64.f) + 1e-5f);
        float rstd1 = rsqrtf(q1 * (1.f / 64.f) + 1e-5f);
        float* od0 = outp + ((size_t)bh * N_ + grow0) * D_;
        float* od1 = od0 + 8 * D_;
        #pragma unroll
        for (int nf = 0; nf < 8; ++nf) {
            int c = (nf << 3) + (tg << 1);
            float ga0 = gamma[c], ga1 = gamma[c + 1];
            float be0 = beta[c],  be1 = beta[c + 1];
            float2 w0, w1;
            w0.x = (v0[2*nf]   - mu0) * rstd0 * ga0 + be0;
            w0.y = (v0[2*nf+1] - mu0) * rstd0 * ga1 + be1;
            w1.x = (v1[2*nf]   - mu1) * rstd1 * ga0 + be0;
            w1.y = (v1[2*nf+1] - mu1) * rstd1 * ga1 + be1;
            *(float2*)&od0[c] = w0;
            *(float2*)&od1[c] = w1;
        }
    }
}

// ---------------- launch -----------------------------------------------------
extern "C" void kernel_launch(void* const* d_in, const int* in_sizes, int n_in,
                              void* d_out, int out_size) {
    const float* x     = (const float*)d_in[0];
    const int*   graph = (const int*)  d_in[1];
    const float* Wh    = (const float*)d_in[2];
    const float* bh    = (const float*)d_in[3];
    const float* Wo    = (const float*)d_in[4];
    const float* bo    = (const float*)d_in[5];
    const float* gamma = (const float*)d_in[6];
    const float* beta  = (const float*)d_in[7];
    float* out = (float*)d_out;

    cudaFuncSetAttribute(attn_mma<1>, cudaFuncAttributeMaxDynamicSharedMemorySize, SMEM_ATT);
    cudaFuncSetAttribute(attn_mma<2>, cudaFuncAttributeMaxDynamicSharedMemorySize, SMEM_ATT);

    build_mask_kernel<<<(N_ * NW_) / 8, 256>>>(graph);
    proj1_kernel<<<dim3(B_ * N_ / 64, H_), 256>>>(x, Wh);
    attn_mma<1><<<dim3(B_ * H_, N_ / 64), 128, SMEM_ATT>>>(bh, nullptr, nullptr, nullptr);
    proj2_kernel<<<(B_ * N_) / 64, 256>>>(Wo);
    attn_mma<2><<<dim3(B_, N_ / 64), 128, SMEM_ATT>>>(bo, gamma, beta, out);
}